// round 8
// baseline (speedup 1.0000x reference)
#include <cuda_runtime.h>
#include <cuda_bf16.h>
#include <cstdint>

// Problem dims
#define HH 128
#define WD 128
#define BB 8
#define DD 512
#define M_TOTAL (HH * WD * BB)   // 131072 rows
#define GUARD 5e-5f
#define CAP 128

// Scratch for Y = X @ W^T + b  (131072 x 512 fp32 = 256 MiB)
__device__ float g_y[(size_t)M_TOTAL * DD];
__device__ int g_ecnt[HH * BB];                   // flagged-e count per (h,b)
__device__ unsigned short g_elist[HH * BB][CAP];  // flagged e's per (h,b)

// ---------------------------------------------------------------------------
// MMA / LDSM macros
// ---------------------------------------------------------------------------
#define MMA_ZERO(d, a, b0, b1)                                               \
    asm volatile(                                                            \
        "mma.sync.aligned.m16n8k16.row.col.f32.bf16.bf16.f32 "              \
        "{%0,%1,%2,%3}, {%4,%5,%6,%7}, {%8,%9}, {%10,%10,%10,%10};"         \
        : "=f"((d)[0]), "=f"((d)[1]), "=f"((d)[2]), "=f"((d)[3])             \
        : "r"((a)[0]), "r"((a)[1]), "r"((a)[2]), "r"((a)[3]),                \
          "r"(b0), "r"(b1), "f"(0.0f))

#define MMA_ACC(d, a, b0, b1)                                                \
    asm volatile(                                                            \
        "mma.sync.aligned.m16n8k16.row.col.f32.bf16.bf16.f32 "              \
        "{%0,%1,%2,%3}, {%4,%5,%6,%7}, {%8,%9}, {%0,%1,%2,%3};"             \
        : "+f"((d)[0]), "+f"((d)[1]), "+f"((d)[2]), "+f"((d)[3])             \
        : "r"((a)[0]), "r"((a)[1]), "r"((a)[2]), "r"((a)[3]),                \
          "r"(b0), "r"(b1))

#define LDSM_X4(r, addr)                                                     \
    asm volatile(                                                            \
        "ldmatrix.sync.aligned.m8n8.x4.shared.b16 {%0,%1,%2,%3}, [%4];"     \
        : "=r"((r)[0]), "=r"((r)[1]), "=r"((r)[2]), "=r"((r)[3])             \
        : "r"(addr))

// SMEM geometry (uint32 units): [row 0..127][kp 0..15] stride 20 (16B-aligned
// rows, conflict-free ldmatrix). 4 arrays per stage (A0, A1, W0, W1), 2 stages.
#define RST  20
#define ARR  (128 * RST)        // 2560 u32 = 10240 B
#define SSTG (4 * ARR)          // stage stride
#define SMEM_GEMM (2 * SSTG * 4)  // 81920 B

__device__ __forceinline__ uint32_t smem_u32(const void* p) {
    uint32_t a;
    asm("{ .reg .u64 t; cvta.to.shared.u64 t, %1; cvt.u32.u64 %0, t; }"
        : "=r"(a) : "l"(p));
    return a;
}

// split 16 fp32 (half k-row) into bf16 hi/lo arrays, wide-store to smem
__device__ __forceinline__ void split_store_half(const float4* p,
                                                 uint32_t* d0, uint32_t* d1) {
    const float* f = (const float*)p;
    uint32_t u0[8], u1[8];
#pragma unroll
    for (int j = 0; j < 8; ++j) {
        float x0 = f[2 * j], x1 = f[2 * j + 1];
        __nv_bfloat16 h0 = __float2bfloat16_rn(x0);
        __nv_bfloat16 h1 = __float2bfloat16_rn(x1);
        __nv_bfloat16 l0 = __float2bfloat16_rn(x0 - __bfloat162float(h0));
        __nv_bfloat16 l1 = __float2bfloat16_rn(x1 - __bfloat162float(h1));
        u0[j] = (uint32_t)__bfloat16_as_ushort(h0) |
                ((uint32_t)__bfloat16_as_ushort(h1) << 16);
        u1[j] = (uint32_t)__bfloat16_as_ushort(l0) |
                ((uint32_t)__bfloat16_as_ushort(l1) << 16);
    }
    ((uint4*)d0)[0] = make_uint4(u0[0], u0[1], u0[2], u0[3]);
    ((uint4*)d0)[1] = make_uint4(u0[4], u0[5], u0[6], u0[7]);
    ((uint4*)d1)[0] = make_uint4(u1[0], u1[1], u1[2], u1[3]);
    ((uint4*)d1)[1] = make_uint4(u1[4], u1[5], u1[6], u1[7]);
}

// ---------------------------------------------------------------------------
// GEMM: Y[m,n] = sum_k X[m,k]*Wlin[n,k] + bias[n]
// bf16 2-level split, 3 passes; per (mt,nt) per 32-k: 3 INDEPENDENT 2-MMA
// chains (max ILP), combined via fp32 RN FADD into register master.
// CTA 128x128, BK=32, 8 warps (2M x 4N), warp tile 64x32, ldmatrix,
// double-buffered smem.
// ---------------------------------------------------------------------------
__global__ __launch_bounds__(256, 1) void gemm_tc_kernel(
    const float* __restrict__ A,
    const float* __restrict__ Wl,
    const float* __restrict__ bias)
{
    extern __shared__ uint32_t smem[];
    const uint32_t sb = smem_u32(smem);

    const int tid  = threadIdx.x;
    const int lane = tid & 31;
    const int wid  = tid >> 5;
    const int wm   = wid >> 2;        // 0..1
    const int wn   = wid & 3;         // 0..3

    const int m0 = blockIdx.y << 7;
    const int n0 = blockIdx.x << 7;

    if (blockIdx.x == 0 && blockIdx.y == 0) {
        for (int i = tid; i < HH * BB; i += 256) g_ecnt[i] = 0;
    }

    // producer: half k-row per thread
    const int row = tid >> 1;
    const int kpo = (tid & 1) << 3;        // kp offset 0 / 8
    const float* ag = A  + (size_t)(m0 + row) * 512 + (kpo << 1);
    const float* wg = Wl + (size_t)(n0 + row) * 512 + (kpo << 1);
    const uint32_t prow = row * RST + kpo;

    // consumer address bases (uint32 offsets)
    const uint32_t a_off = ((wm << 6) + (lane & 15)) * RST + ((lane >> 4) << 2);
    const uint32_t b_off = ((wn << 5) + ((lane >> 4) << 3) + (lane & 7)) * RST +
                           (((lane >> 3) & 1) << 2);

    float acc[4][4][4];
#pragma unroll
    for (int mt = 0; mt < 4; ++mt)
#pragma unroll
        for (int nt = 0; nt < 4; ++nt)
#pragma unroll
            for (int r = 0; r < 4; ++r) acc[mt][nt][r] = 0.0f;

    float4 pa[4], pw[4];
#pragma unroll
    for (int j = 0; j < 4; ++j) {
        pa[j] = ((const float4*)ag)[j];
        pw[j] = ((const float4*)wg)[j];
    }
    // prologue: fill stage 0
    split_store_half(pa, smem + prow,           smem + ARR + prow);
    split_store_half(pw, smem + 2 * ARR + prow, smem + 3 * ARR + prow);
    __syncthreads();

#pragma unroll 2
    for (int it = 0; it < 16; ++it) {
        const uint32_t stg = (it & 1) ? (uint32_t)SSTG : 0u;

        if (it < 15) {
            const float* an  = ag + (it + 1) * 32;
            const float* wg2 = wg + (it + 1) * 32;
#pragma unroll
            for (int j = 0; j < 4; ++j) {
                pa[j] = ((const float4*)an)[j];
                pw[j] = ((const float4*)wg2)[j];
            }
        }

        // ---- MMA phase on stage stg ----
        // B fragments: [lvl][ks][ntp][4]  (regs 0,1 = nt even; 2,3 = nt odd)
        uint32_t bfr[2][2][2][4];
#pragma unroll
        for (int lvl = 0; lvl < 2; ++lvl)
#pragma unroll
            for (int ks = 0; ks < 2; ++ks)
#pragma unroll
                for (int ntp = 0; ntp < 2; ++ntp) {
                    const uint32_t addr = sb + 4 * (stg + (2 + lvl) * ARR +
                                                    b_off + ks * 8 + ntp * 320);
                    LDSM_X4(bfr[lvl][ks][ntp], addr);
                }

#pragma unroll
        for (int mt = 0; mt < 4; ++mt) {
            uint32_t af[2][2][4];   // [lvl][ks][4]
#pragma unroll
            for (int lvl = 0; lvl < 2; ++lvl)
#pragma unroll
                for (int ks = 0; ks < 2; ++ks) {
                    const uint32_t addr = sb + 4 * (stg + lvl * ARR + a_off +
                                                    ks * 8 + mt * 320);
                    LDSM_X4(af[lvl][ks], addr);
                }
#pragma unroll
            for (int nt = 0; nt < 4; ++nt) {
                const int ntp = nt >> 1, so = (nt & 1) << 1;
                float c0[4], c1[4], c2[4];
                // 3 independent chains (one per pass), 2 links each
                MMA_ZERO(c0, af[1][0], bfr[0][0][ntp][so], bfr[0][0][ntp][so + 1]);
                MMA_ZERO(c1, af[0][0], bfr[1][0][ntp][so], bfr[1][0][ntp][so + 1]);
                MMA_ZERO(c2, af[0][0], bfr[0][0][ntp][so], bfr[0][0][ntp][so + 1]);
                MMA_ACC(c0, af[1][1], bfr[0][1][ntp][so], bfr[0][1][ntp][so + 1]);
                MMA_ACC(c1, af[0][1], bfr[1][1][ntp][so], bfr[1][1][ntp][so + 1]);
                MMA_ACC(c2, af[0][1], bfr[0][1][ntp][so], bfr[0][1][ntp][so + 1]);
#pragma unroll
                for (int r = 0; r < 4; ++r)
                    acc[mt][nt][r] += (c0[r] + c1[r]) + c2[r];
            }
        }

        // ---- producer phase: fill other stage ----
        if (it < 15) {
            const uint32_t nst = (it & 1) ? 0u : (uint32_t)SSTG;
            split_store_half(pa, smem + nst + prow, smem + nst + ARR + prow);
            split_store_half(pw, smem + nst + 2 * ARR + prow,
                                 smem + nst + 3 * ARR + prow);
        }
        __syncthreads();
    }

    // epilogue: add bias, write Y
    const int q = lane & 3;
    const int r = lane >> 2;
#pragma unroll
    for (int nt = 0; nt < 4; ++nt) {
        const int col = n0 + (wn << 5) + (nt << 3) + (q << 1);
        const float2 bb = *(const float2*)&bias[col];
#pragma unroll
        for (int mt = 0; mt < 4; ++mt) {
            const int rrow = m0 + (wm << 6) + (mt << 4) + r;
            float2 v0, v1;
            v0.x = acc[mt][nt][0] + bb.x;
            v0.y = acc[mt][nt][1] + bb.y;
            v1.x = acc[mt][nt][2] + bb.x;
            v1.y = acc[mt][nt][3] + bb.y;
            *(float2*)&g_y[(size_t)rrow * 512 + col]       = v0;
            *(float2*)&g_y[(size_t)(rrow + 8) * 512 + col] = v1;
        }
    }
}

// ---------------------------------------------------------------------------
// Bidirectional LIF scan + marginal-column flagging (per-(h,b) e-lists)
// ---------------------------------------------------------------------------
__global__ __launch_bounds__(256) void lif_scan_kernel(float* __restrict__ out)
{
    const int g = blockIdx.x * 256 + threadIdx.x;
    const int e = g & (DD - 1);
    const int b = (g >> 9) & (BB - 1);
    const int h = g >> 12;

    const size_t base = ((size_t)h * WD * BB + b) * DD + e;
    const float* yp = g_y + base;
    const size_t wstride = (size_t)BB * DD;

    unsigned fw[4] = {0u, 0u, 0u, 0u};
    unsigned bw[4] = {0u, 0u, 0u, 0u};
    bool flag = false;

    {
        float v = 0.0f;
#pragma unroll 8
        for (int w = 0; w < WD; ++w) {
            float yt = yp[(size_t)w * wstride];
            v = v + (yt - v) * 0.5f;
            flag |= (fabsf(v - 1.0f) < GUARD);
            if (v - 1.0f >= 0.0f) {
                fw[w >> 5] |= 1u << (w & 31);
                v = 0.0f;
            }
        }
    }
    {
        float v = 0.0f;
#pragma unroll 8
        for (int w = WD - 1; w >= 0; --w) {
            float yt = yp[(size_t)w * wstride];
            v = v + (yt - v) * 0.5f;
            flag |= (fabsf(v - 1.0f) < GUARD);
            if (v - 1.0f >= 0.0f) {
                bw[w >> 5] |= 1u << (w & 31);
                v = 0.0f;
            }
        }
    }

    float* op = out + base;
#pragma unroll 8
    for (int w = 0; w < WD; ++w) {
        float s = (float)(((fw[w >> 5] >> (w & 31)) & 1u) +
                          ((bw[w >> 5] >> (w & 31)) & 1u));
        op[(size_t)w * wstride] = s;
    }

    if (flag) {
        const int hb = g >> 9;
        int idx = atomicAdd(&g_ecnt[hb], 1);
        if (idx < CAP) g_elist[hb][idx] = (unsigned short)e;
    }
}

// ---------------------------------------------------------------------------
// Correction: one block per (h,b); recompute flagged e-columns exactly
// (ascending-k fp32 scalar FMA), redo both scans, overwrite out.
// ---------------------------------------------------------------------------
#define CSM_XS 0
#define CSM_WS (64 * 128)
#define CSM_YB (CSM_WS + 8 * 512)
#define CSM_TOTAL ((CSM_YB + 8 * 128) * 4)   // 53248 B

__global__ __launch_bounds__(256) void correct_kernel(
    const float* __restrict__ x,
    const float* __restrict__ Wl,
    const float* __restrict__ bias,
    float* __restrict__ out)
{
    extern __shared__ float csm[];
    float* xs   = csm + CSM_XS;   // [kk 0..63][w 0..127]
    float* ws   = csm + CSM_WS;   // [warp][512]
    float* ybuf = csm + CSM_YB;   // [warp][128]

    const int hb = blockIdx.x;
    int cnt = g_ecnt[hb];
    if (cnt <= 0) return;
    if (cnt > CAP) cnt = CAP;

    const int h = hb >> 3, b = hb & 7;
    const int tid = threadIdx.x, wrp = tid >> 5, lane = tid & 31;
    const size_t cbase = ((size_t)(h * WD) * BB + b) * DD;

    for (int ebase = 0; ebase < cnt; ebase += 8) {
        int e = -1;
        float be = 0.0f;
        if (ebase + wrp < cnt) {
            e = g_elist[hb][ebase + wrp];
            be = bias[e];
            const float4* wr = (const float4*)(Wl + (size_t)e * 512);
            float4* wd = (float4*)(ws + wrp * 512);
            for (int j = lane; j < 128; j += 32) wd[j] = wr[j];
        }

        float a0 = 0.f, a1 = 0.f, a2 = 0.f, a3 = 0.f;
        for (int ck = 0; ck < 8; ++ck) {
            __syncthreads();
#pragma unroll
            for (int i = 0; i < 2; ++i) {
                const int w = (tid >> 2) + i * 64;
                const float4* xr = (const float4*)(x + cbase +
                                                   (size_t)w * 4096 + ck * 64);
#pragma unroll
                for (int j = 0; j < 4; ++j) {
                    const int k4 = (tid & 3) + j * 4;
                    float4 v = xr[k4];
                    xs[(k4 * 4 + 0) * 128 + w] = v.x;
                    xs[(k4 * 4 + 1) * 128 + w] = v.y;
                    xs[(k4 * 4 + 2) * 128 + w] = v.z;
                    xs[(k4 * 4 + 3) * 128 + w] = v.w;
                }
            }
            __syncthreads();
            if (e >= 0) {
                const float* wc = ws + wrp * 512 + ck * 64;
                for (int kk = 0; kk < 64; ++kk) {
                    const float wv = wc[kk];
                    a0 = fmaf(xs[kk * 128 + lane],      wv, a0);
                    a1 = fmaf(xs[kk * 128 + lane + 32], wv, a1);
                    a2 = fmaf(xs[kk * 128 + lane + 64], wv, a2);
                    a3 = fmaf(xs[kk * 128 + lane + 96], wv, a3);
                }
            }
        }

        unsigned bits[4] = {0u, 0u, 0u, 0u};
        if (e >= 0) {
            ybuf[wrp * 128 + lane]      = a0 + be;
            ybuf[wrp * 128 + lane + 32] = a1 + be;
            ybuf[wrp * 128 + lane + 64] = a2 + be;
            ybuf[wrp * 128 + lane + 96] = a3 + be;
        }
        __syncwarp();
        if (e >= 0 && lane < 2) {
            float v = 0.0f;
            for (int i = 0; i < WD; ++i) {
                const int w = lane ? (WD - 1 - i) : i;
                float yt = ybuf[wrp * 128 + w];
                v = v + (yt - v) * 0.5f;
                if (v - 1.0f >= 0.0f) { bits[w >> 5] |= 1u << (w & 31); v = 0.0f; }
            }
        }
        unsigned fwv[4], bwv[4];
#pragma unroll
        for (int i = 0; i < 4; ++i) {
            fwv[i] = __shfl_sync(0xFFFFFFFFu, bits[i], 0);
            bwv[i] = __shfl_sync(0xFFFFFFFFu, bits[i], 1);
        }
        if (e >= 0) {
#pragma unroll
            for (int c = 0; c < 4; ++c) {
                const int w = lane + 32 * c;
                float s = (float)(((fwv[w >> 5] >> (w & 31)) & 1u) +
                                  ((bwv[w >> 5] >> (w & 31)) & 1u));
                out[cbase + (size_t)w * 4096 + e] = s;
            }
        }
        __syncthreads();
    }
}

extern "C" void kernel_launch(void* const* d_in, const int* in_sizes, int n_in,
                              void* d_out, int out_size)
{
    const float* x    = (const float*)d_in[0];   // (16384, 8, 512) fp32
    const float* Wlin = (const float*)d_in[1];   // (512, 512) fp32
    const float* blin = (const float*)d_in[2];   // (512,) fp32
    float* out = (float*)d_out;

    cudaFuncSetAttribute(gemm_tc_kernel,
                         cudaFuncAttributeMaxDynamicSharedMemorySize, SMEM_GEMM);
    cudaFuncSetAttribute(correct_kernel,
                         cudaFuncAttributeMaxDynamicSharedMemorySize, CSM_TOTAL);

    dim3 ggrid(4, 1024);   // N/128, M/128
    gemm_tc_kernel<<<ggrid, 256, SMEM_GEMM>>>(x, Wlin, blin);

    lif_scan_kernel<<<(HH * BB * DD) / 256, 256>>>(out);

    correct_kernel<<<HH * BB, 256, CSM_TOTAL>>>(x, Wlin, blin, out);
}

// round 9
// speedup vs baseline: 1.2360x; 1.2360x over previous
#include <cuda_runtime.h>
#include <cuda_bf16.h>
#include <cstdint>

// Problem dims
#define HH 128
#define WD 128
#define BB 8
#define DD 512
#define M_TOTAL (HH * WD * BB)   // 131072 rows
#define GUARD 5e-5f
#define CAP 128

// Scratch for Y = X @ W^T + b  (131072 x 512 fp32 = 256 MiB)
__device__ float g_y[(size_t)M_TOTAL * DD];
__device__ int g_ecnt[HH * BB];                   // flagged-e count per (h,b)
__device__ unsigned short g_elist[HH * BB][CAP];  // flagged e's per (h,b)

// ---------------------------------------------------------------------------
// MMA / LDSM macros
// ---------------------------------------------------------------------------
#define MMA_ZERO(d, a, b0, b1)                                               \
    asm volatile(                                                            \
        "mma.sync.aligned.m16n8k16.row.col.f32.bf16.bf16.f32 "              \
        "{%0,%1,%2,%3}, {%4,%5,%6,%7}, {%8,%9}, {%10,%10,%10,%10};"         \
        : "=f"((d)[0]), "=f"((d)[1]), "=f"((d)[2]), "=f"((d)[3])             \
        : "r"((a)[0]), "r"((a)[1]), "r"((a)[2]), "r"((a)[3]),                \
          "r"(b0), "r"(b1), "f"(0.0f))

#define MMA_ACC(d, a, b0, b1)                                                \
    asm volatile(                                                            \
        "mma.sync.aligned.m16n8k16.row.col.f32.bf16.bf16.f32 "              \
        "{%0,%1,%2,%3}, {%4,%5,%6,%7}, {%8,%9}, {%0,%1,%2,%3};"             \
        : "+f"((d)[0]), "+f"((d)[1]), "+f"((d)[2]), "+f"((d)[3])             \
        : "r"((a)[0]), "r"((a)[1]), "r"((a)[2]), "r"((a)[3]),                \
          "r"(b0), "r"(b1))

#define LDSM_X4(r, addr)                                                     \
    asm volatile(                                                            \
        "ldmatrix.sync.aligned.m8n8.x4.shared.b16 {%0,%1,%2,%3}, [%4];"     \
        : "=r"((r)[0]), "=r"((r)[1]), "=r"((r)[2]), "=r"((r)[3])             \
        : "r"(addr))

// SMEM geometry (uint32 units): [row 0..127][kp 0..15] stride 20 (16B-aligned
// rows, conflict-free ldmatrix). 4 arrays per stage (A0, A1, W0, W1), 2 stages.
#define RST  20
#define ARR  (128 * RST)        // 2560 u32 = 10240 B
#define SSTG (4 * ARR)          // stage stride
#define SMEM_GEMM (2 * SSTG * 4)  // 81920 B

__device__ __forceinline__ uint32_t smem_u32(const void* p) {
    uint32_t a;
    asm("{ .reg .u64 t; cvta.to.shared.u64 t, %1; cvt.u32.u64 %0, t; }"
        : "=r"(a) : "l"(p));
    return a;
}

// split 8 fp32 (quarter k-row) into bf16 hi/lo, one uint4 store per level
__device__ __forceinline__ void split_store_q(const float4* p,
                                              uint32_t* d0, uint32_t* d1) {
    const float* f = (const float*)p;
    uint32_t u0[4], u1[4];
#pragma unroll
    for (int j = 0; j < 4; ++j) {
        float x0 = f[2 * j], x1 = f[2 * j + 1];
        __nv_bfloat16 h0 = __float2bfloat16_rn(x0);
        __nv_bfloat16 h1 = __float2bfloat16_rn(x1);
        __nv_bfloat16 l0 = __float2bfloat16_rn(x0 - __bfloat162float(h0));
        __nv_bfloat16 l1 = __float2bfloat16_rn(x1 - __bfloat162float(h1));
        u0[j] = (uint32_t)__bfloat16_as_ushort(h0) |
                ((uint32_t)__bfloat16_as_ushort(h1) << 16);
        u1[j] = (uint32_t)__bfloat16_as_ushort(l0) |
                ((uint32_t)__bfloat16_as_ushort(l1) << 16);
    }
    *(uint4*)d0 = make_uint4(u0[0], u0[1], u0[2], u0[3]);
    *(uint4*)d1 = make_uint4(u1[0], u1[1], u1[2], u1[3]);
}

// ---------------------------------------------------------------------------
// GEMM: Y[m,n] = sum_k X[m,k]*Wlin[n,k] + bias[n]
// bf16 2-level split, 3 passes; 6-MMA fresh chain per (mt,nt) per 32-k, FADD
// master. CTA 128x128, BK=32, 16 warps (2M x 8N), warp tile 64x16, ldmatrix,
// double-buffered smem, 512 threads (4 warps/SMSP).
// ---------------------------------------------------------------------------
__global__ __launch_bounds__(512, 1) void gemm_tc_kernel(
    const float* __restrict__ A,
    const float* __restrict__ Wl,
    const float* __restrict__ bias)
{
    extern __shared__ uint32_t smem[];
    const uint32_t sb = smem_u32(smem);

    const int tid  = threadIdx.x;
    const int lane = tid & 31;
    const int wid  = tid >> 5;
    const int wm   = wid >> 3;        // 0..1
    const int wn   = wid & 7;         // 0..7

    const int m0 = blockIdx.y << 7;
    const int n0 = blockIdx.x << 7;

    if (blockIdx.x == 0 && blockIdx.y == 0) {
        for (int i = tid; i < HH * BB; i += 512) g_ecnt[i] = 0;
    }

    // producer: quarter k-row per thread (8 floats of A, 8 of W)
    const int row = tid >> 2;
    const int kpo = (tid & 3) << 2;        // kp offset 0/4/8/12
    const float* ag = A  + (size_t)(m0 + row) * 512 + (kpo << 1);
    const float* wg = Wl + (size_t)(n0 + row) * 512 + (kpo << 1);
    const uint32_t prow = row * RST + kpo;

    // consumer address bases (uint32 offsets)
    const uint32_t a_off = ((wm << 6) + (lane & 15)) * RST + ((lane >> 4) << 2);
    const uint32_t b_off = ((wn << 4) + ((lane >> 4) << 3) + (lane & 7)) * RST +
                           (((lane >> 3) & 1) << 2);

    float acc[4][2][4];
#pragma unroll
    for (int mt = 0; mt < 4; ++mt)
#pragma unroll
        for (int nt = 0; nt < 2; ++nt)
#pragma unroll
            for (int r = 0; r < 4; ++r) acc[mt][nt][r] = 0.0f;

    float4 pa[2], pw[2];
    pa[0] = ((const float4*)ag)[0];
    pa[1] = ((const float4*)ag)[1];
    pw[0] = ((const float4*)wg)[0];
    pw[1] = ((const float4*)wg)[1];

    // prologue: fill stage 0
    split_store_q(pa, smem + prow,           smem + ARR + prow);
    split_store_q(pw, smem + 2 * ARR + prow, smem + 3 * ARR + prow);
    __syncthreads();

#pragma unroll 2
    for (int it = 0; it < 16; ++it) {
        const uint32_t stg = (it & 1) ? (uint32_t)SSTG : 0u;

        if (it < 15) {
            const float* an  = ag + (it + 1) * 32;
            const float* wg2 = wg + (it + 1) * 32;
            pa[0] = ((const float4*)an)[0];
            pa[1] = ((const float4*)an)[1];
            pw[0] = ((const float4*)wg2)[0];
            pw[1] = ((const float4*)wg2)[1];
        }

        // ---- MMA phase on stage stg ----
        // B fragments: [lvl][ks][4]; regs 0,1 = nt0 (n8 lo), 2,3 = nt1 (n8 hi)
        uint32_t bfr[2][2][4];
#pragma unroll
        for (int lvl = 0; lvl < 2; ++lvl)
#pragma unroll
            for (int ks = 0; ks < 2; ++ks) {
                const uint32_t addr = sb + 4 * (stg + (2 + lvl) * ARR +
                                                b_off + ks * 8);
                LDSM_X4(bfr[lvl][ks], addr);
            }

#pragma unroll
        for (int mt = 0; mt < 4; ++mt) {
            uint32_t af[2][2][4];   // [lvl][ks][4]
#pragma unroll
            for (int lvl = 0; lvl < 2; ++lvl)
#pragma unroll
                for (int ks = 0; ks < 2; ++ks) {
                    const uint32_t addr = sb + 4 * (stg + lvl * ARR + a_off +
                                                    ks * 8 + mt * 320);
                    LDSM_X4(af[lvl][ks], addr);
                }
#pragma unroll
            for (int nt = 0; nt < 2; ++nt) {
                const int so = nt << 1;
                float d[4];
                // 6-MMA fresh chain, small terms first (proven R5/R7 ordering)
                MMA_ZERO(d, af[1][0], bfr[0][0][so], bfr[0][0][so + 1]);  // a1b0 k0
                MMA_ACC(d, af[1][1], bfr[0][1][so], bfr[0][1][so + 1]);   // a1b0 k1
                MMA_ACC(d, af[0][0], bfr[1][0][so], bfr[1][0][so + 1]);   // a0b1 k0
                MMA_ACC(d, af[0][1], bfr[1][1][so], bfr[1][1][so + 1]);   // a0b1 k1
                MMA_ACC(d, af[0][0], bfr[0][0][so], bfr[0][0][so + 1]);   // a0b0 k0
                MMA_ACC(d, af[0][1], bfr[0][1][so], bfr[0][1][so + 1]);   // a0b0 k1
                acc[mt][nt][0] += d[0];
                acc[mt][nt][1] += d[1];
                acc[mt][nt][2] += d[2];
                acc[mt][nt][3] += d[3];
            }
        }

        // ---- producer phase: fill other stage ----
        if (it < 15) {
            const uint32_t nst = (it & 1) ? 0u : (uint32_t)SSTG;
            split_store_q(pa, smem + nst + prow, smem + nst + ARR + prow);
            split_store_q(pw, smem + nst + 2 * ARR + prow,
                              smem + nst + 3 * ARR + prow);
        }
        __syncthreads();
    }

    // epilogue: add bias, write Y
    const int q = lane & 3;
    const int r = lane >> 2;
#pragma unroll
    for (int nt = 0; nt < 2; ++nt) {
        const int col = n0 + (wn << 4) + (nt << 3) + (q << 1);
        const float2 bb = *(const float2*)&bias[col];
#pragma unroll
        for (int mt = 0; mt < 4; ++mt) {
            const int rrow = m0 + (wm << 6) + (mt << 4) + r;
            float2 v0, v1;
            v0.x = acc[mt][nt][0] + bb.x;
            v0.y = acc[mt][nt][1] + bb.y;
            v1.x = acc[mt][nt][2] + bb.x;
            v1.y = acc[mt][nt][3] + bb.y;
            *(float2*)&g_y[(size_t)rrow * 512 + col]       = v0;
            *(float2*)&g_y[(size_t)(rrow + 8) * 512 + col] = v1;
        }
    }
}

// ---------------------------------------------------------------------------
// Bidirectional LIF scan + marginal-column flagging (per-(h,b) e-lists)
// ---------------------------------------------------------------------------
__global__ __launch_bounds__(256) void lif_scan_kernel(float* __restrict__ out)
{
    const int g = blockIdx.x * 256 + threadIdx.x;
    const int e = g & (DD - 1);
    const int b = (g >> 9) & (BB - 1);
    const int h = g >> 12;

    const size_t base = ((size_t)h * WD * BB + b) * DD + e;
    const float* yp = g_y + base;
    const size_t wstride = (size_t)BB * DD;

    unsigned fw[4] = {0u, 0u, 0u, 0u};
    unsigned bw[4] = {0u, 0u, 0u, 0u};
    bool flag = false;

    {
        float v = 0.0f;
#pragma unroll 8
        for (int w = 0; w < WD; ++w) {
            float yt = yp[(size_t)w * wstride];
            v = v + (yt - v) * 0.5f;
            flag |= (fabsf(v - 1.0f) < GUARD);
            if (v - 1.0f >= 0.0f) {
                fw[w >> 5] |= 1u << (w & 31);
                v = 0.0f;
            }
        }
    }
    {
        float v = 0.0f;
#pragma unroll 8
        for (int w = WD - 1; w >= 0; --w) {
            float yt = yp[(size_t)w * wstride];
            v = v + (yt - v) * 0.5f;
            flag |= (fabsf(v - 1.0f) < GUARD);
            if (v - 1.0f >= 0.0f) {
                bw[w >> 5] |= 1u << (w & 31);
                v = 0.0f;
            }
        }
    }

    float* op = out + base;
#pragma unroll 8
    for (int w = 0; w < WD; ++w) {
        float s = (float)(((fw[w >> 5] >> (w & 31)) & 1u) +
                          ((bw[w >> 5] >> (w & 31)) & 1u));
        op[(size_t)w * wstride] = s;
    }

    if (flag) {
        const int hb = g >> 9;
        int idx = atomicAdd(&g_ecnt[hb], 1);
        if (idx < CAP) g_elist[hb][idx] = (unsigned short)e;
    }
}

// ---------------------------------------------------------------------------
// Correction: one block per (h,b); recompute flagged e-columns exactly
// (ascending-k fp32 scalar FMA), redo both scans, overwrite out.
// ---------------------------------------------------------------------------
#define CSM_XS 0
#define CSM_WS (64 * 128)
#define CSM_YB (CSM_WS + 8 * 512)
#define CSM_TOTAL ((CSM_YB + 8 * 128) * 4)   // 53248 B

__global__ __launch_bounds__(256) void correct_kernel(
    const float* __restrict__ x,
    const float* __restrict__ Wl,
    const float* __restrict__ bias,
    float* __restrict__ out)
{
    extern __shared__ float csm[];
    float* xs   = csm + CSM_XS;   // [kk 0..63][w 0..127]
    float* ws   = csm + CSM_WS;   // [warp][512]
    float* ybuf = csm + CSM_YB;   // [warp][128]

    const int hb = blockIdx.x;
    int cnt = g_ecnt[hb];
    if (cnt <= 0) return;
    if (cnt > CAP) cnt = CAP;

    const int h = hb >> 3, b = hb & 7;
    const int tid = threadIdx.x, wrp = tid >> 5, lane = tid & 31;
    const size_t cbase = ((size_t)(h * WD) * BB + b) * DD;

    for (int ebase = 0; ebase < cnt; ebase += 8) {
        int e = -1;
        float be = 0.0f;
        if (ebase + wrp < cnt) {
            e = g_elist[hb][ebase + wrp];
            be = bias[e];
            const float4* wr = (const float4*)(Wl + (size_t)e * 512);
            float4* wd = (float4*)(ws + wrp * 512);
            for (int j = lane; j < 128; j += 32) wd[j] = wr[j];
        }

        float a0 = 0.f, a1 = 0.f, a2 = 0.f, a3 = 0.f;
        for (int ck = 0; ck < 8; ++ck) {
            __syncthreads();
#pragma unroll
            for (int i = 0; i < 2; ++i) {
                const int w = (tid >> 2) + i * 64;
                const float4* xr = (const float4*)(x + cbase +
                                                   (size_t)w * 4096 + ck * 64);
#pragma unroll
                for (int j = 0; j < 4; ++j) {
                    const int k4 = (tid & 3) + j * 4;
                    float4 v = xr[k4];
                    xs[(k4 * 4 + 0) * 128 + w] = v.x;
                    xs[(k4 * 4 + 1) * 128 + w] = v.y;
                    xs[(k4 * 4 + 2) * 128 + w] = v.z;
                    xs[(k4 * 4 + 3) * 128 + w] = v.w;
                }
            }
            __syncthreads();
            if (e >= 0) {
                const float* wc = ws + wrp * 512 + ck * 64;
                for (int kk = 0; kk < 64; ++kk) {
                    const float wv = wc[kk];
                    a0 = fmaf(xs[kk * 128 + lane],      wv, a0);
                    a1 = fmaf(xs[kk * 128 + lane + 32], wv, a1);
                    a2 = fmaf(xs[kk * 128 + lane + 64], wv, a2);
                    a3 = fmaf(xs[kk * 128 + lane + 96], wv, a3);
                }
            }
        }

        unsigned bits[4] = {0u, 0u, 0u, 0u};
        if (e >= 0) {
            ybuf[wrp * 128 + lane]      = a0 + be;
            ybuf[wrp * 128 + lane + 32] = a1 + be;
            ybuf[wrp * 128 + lane + 64] = a2 + be;
            ybuf[wrp * 128 + lane + 96] = a3 + be;
        }
        __syncwarp();
        if (e >= 0 && lane < 2) {
            float v = 0.0f;
            for (int i = 0; i < WD; ++i) {
                const int w = lane ? (WD - 1 - i) : i;
                float yt = ybuf[wrp * 128 + w];
                v = v + (yt - v) * 0.5f;
                if (v - 1.0f >= 0.0f) { bits[w >> 5] |= 1u << (w & 31); v = 0.0f; }
            }
        }
        unsigned fwv[4], bwv[4];
#pragma unroll
        for (int i = 0; i < 4; ++i) {
            fwv[i] = __shfl_sync(0xFFFFFFFFu, bits[i], 0);
            bwv[i] = __shfl_sync(0xFFFFFFFFu, bits[i], 1);
        }
        if (e >= 0) {
#pragma unroll
            for (int c = 0; c < 4; ++c) {
                const int w = lane + 32 * c;
                float s = (float)(((fwv[w >> 5] >> (w & 31)) & 1u) +
                                  ((bwv[w >> 5] >> (w & 31)) & 1u));
                out[cbase + (size_t)w * 4096 + e] = s;
            }
        }
        __syncthreads();
    }
}

extern "C" void kernel_launch(void* const* d_in, const int* in_sizes, int n_in,
                              void* d_out, int out_size)
{
    const float* x    = (const float*)d_in[0];   // (16384, 8, 512) fp32
    const float* Wlin = (const float*)d_in[1];   // (512, 512) fp32
    const float* blin = (const float*)d_in[2];   // (512,) fp32
    float* out = (float*)d_out;

    cudaFuncSetAttribute(gemm_tc_kernel,
                         cudaFuncAttributeMaxDynamicSharedMemorySize, SMEM_GEMM);
    cudaFuncSetAttribute(correct_kernel,
                         cudaFuncAttributeMaxDynamicSharedMemorySize, CSM_TOTAL);

    dim3 ggrid(4, 1024);   // N/128, M/128
    gemm_tc_kernel<<<ggrid, 512, SMEM_GEMM>>>(x, Wlin, blin);

    lif_scan_kernel<<<(HH * BB * DD) / 256, 256>>>(out);

    correct_kernel<<<HH * BB, 256, CSM_TOTAL>>>(x, Wlin, blin, out);
}

// round 10
// speedup vs baseline: 1.3236x; 1.0709x over previous
#include <cuda_runtime.h>
#include <cuda_fp16.h>
#include <cstdint>

// Problem dims
#define HH 128
#define WD 128
#define BB 8
#define DD 512
#define M_TOTAL (HH * WD * BB)   // 131072 rows
#define GUARD 2e-5f
#define CAP 128

// Scratch for Y = X @ W^T + b  (131072 x 512 fp32 = 256 MiB)
__device__ float g_y[(size_t)M_TOTAL * DD];
__device__ int g_ecnt[HH * BB];                   // flagged-e count per (h,b)
__device__ unsigned short g_elist[HH * BB][CAP];  // flagged e's per (h,b)

// ---------------------------------------------------------------------------
// MMA / LDSM macros (fp16 inputs, fp32 accum)
// ---------------------------------------------------------------------------
#define MMA_ZERO(d, a, b0, b1)                                               \
    asm volatile(                                                            \
        "mma.sync.aligned.m16n8k16.row.col.f32.f16.f16.f32 "                \
        "{%0,%1,%2,%3}, {%4,%5,%6,%7}, {%8,%9}, {%10,%10,%10,%10};"         \
        : "=f"((d)[0]), "=f"((d)[1]), "=f"((d)[2]), "=f"((d)[3])             \
        : "r"((a)[0]), "r"((a)[1]), "r"((a)[2]), "r"((a)[3]),                \
          "r"(b0), "r"(b1), "f"(0.0f))

#define MMA_ACC(d, a, b0, b1)                                                \
    asm volatile(                                                            \
        "mma.sync.aligned.m16n8k16.row.col.f32.f16.f16.f32 "                \
        "{%0,%1,%2,%3}, {%4,%5,%6,%7}, {%8,%9}, {%0,%1,%2,%3};"             \
        : "+f"((d)[0]), "+f"((d)[1]), "+f"((d)[2]), "+f"((d)[3])             \
        : "r"((a)[0]), "r"((a)[1]), "r"((a)[2]), "r"((a)[3]),                \
          "r"(b0), "r"(b1))

#define LDSM_X4(r, addr)                                                     \
    asm volatile(                                                            \
        "ldmatrix.sync.aligned.m8n8.x4.shared.b16 {%0,%1,%2,%3}, [%4];"     \
        : "=r"((r)[0]), "=r"((r)[1]), "=r"((r)[2]), "=r"((r)[3])             \
        : "r"(addr))

// SMEM geometry (uint32 units): [row 0..127][kp 0..15] stride 20 (16B-aligned
// rows, conflict-free ldmatrix). 4 arrays per stage (A0, A1, W0, W1), 2 stages.
#define RST  20
#define ARR  (128 * RST)        // 2560 u32 = 10240 B
#define SSTG (4 * ARR)          // stage stride
#define SMEM_GEMM (2 * SSTG * 4)  // 81920 B

__device__ __forceinline__ uint32_t smem_u32(const void* p) {
    uint32_t a;
    asm("{ .reg .u64 t; cvta.to.shared.u64 t, %1; cvt.u32.u64 %0, t; }"
        : "=r"(a) : "l"(p));
    return a;
}

// split 8 fp32 (quarter k-row) into fp16 hi/lo, one uint4 store per level
__device__ __forceinline__ void split_store_q(const float4* p,
                                              uint32_t* d0, uint32_t* d1) {
    const float* f = (const float*)p;
    uint32_t u0[4], u1[4];
#pragma unroll
    for (int j = 0; j < 4; ++j) {
        float x0 = f[2 * j], x1 = f[2 * j + 1];
        __half h0 = __float2half_rn(x0);
        __half h1 = __float2half_rn(x1);
        __half l0 = __float2half_rn(x0 - __half2float(h0));
        __half l1 = __float2half_rn(x1 - __half2float(h1));
        u0[j] = (uint32_t)__half_as_ushort(h0) |
                ((uint32_t)__half_as_ushort(h1) << 16);
        u1[j] = (uint32_t)__half_as_ushort(l0) |
                ((uint32_t)__half_as_ushort(l1) << 16);
    }
    *(uint4*)d0 = make_uint4(u0[0], u0[1], u0[2], u0[3]);
    *(uint4*)d1 = make_uint4(u1[0], u1[1], u1[2], u1[3]);
}

// ---------------------------------------------------------------------------
// GEMM: Y[m,n] = sum_k X[m,k]*Wlin[n,k] + bias[n]
// fp16 2-level split, 3 passes; 6-MMA fresh chain per (mt,nt) per 32-k, FADD
// master. CTA 128x128, BK=32, 16 warps (2M x 8N), warp tile 64x16, ldmatrix,
// double-buffered smem, 512 threads (4 warps/SMSP).
// ---------------------------------------------------------------------------
__global__ __launch_bounds__(512, 1) void gemm_tc_kernel(
    const float* __restrict__ A,
    const float* __restrict__ Wl,
    const float* __restrict__ bias)
{
    extern __shared__ uint32_t smem[];
    const uint32_t sb = smem_u32(smem);

    const int tid  = threadIdx.x;
    const int lane = tid & 31;
    const int wid  = tid >> 5;
    const int wm   = wid >> 3;        // 0..1
    const int wn   = wid & 7;         // 0..7

    const int m0 = blockIdx.y << 7;
    const int n0 = blockIdx.x << 7;

    if (blockIdx.x == 0 && blockIdx.y == 0) {
        for (int i = tid; i < HH * BB; i += 512) g_ecnt[i] = 0;
    }

    // producer: quarter k-row per thread (8 floats of A, 8 of W)
    const int row = tid >> 2;
    const int kpo = (tid & 3) << 2;        // kp offset 0/4/8/12
    const float* ag = A  + (size_t)(m0 + row) * 512 + (kpo << 1);
    const float* wg = Wl + (size_t)(n0 + row) * 512 + (kpo << 1);
    const uint32_t prow = row * RST + kpo;

    // consumer address bases (uint32 offsets)
    const uint32_t a_off = ((wm << 6) + (lane & 15)) * RST + ((lane >> 4) << 2);
    const uint32_t b_off = ((wn << 4) + ((lane >> 4) << 3) + (lane & 7)) * RST +
                           (((lane >> 3) & 1) << 2);

    float acc[4][2][4];
#pragma unroll
    for (int mt = 0; mt < 4; ++mt)
#pragma unroll
        for (int nt = 0; nt < 2; ++nt)
#pragma unroll
            for (int r = 0; r < 4; ++r) acc[mt][nt][r] = 0.0f;

    float4 pa[2], pw[2];
    pa[0] = ((const float4*)ag)[0];
    pa[1] = ((const float4*)ag)[1];
    pw[0] = ((const float4*)wg)[0];
    pw[1] = ((const float4*)wg)[1];

    // prologue: fill stage 0
    split_store_q(pa, smem + prow,           smem + ARR + prow);
    split_store_q(pw, smem + 2 * ARR + prow, smem + 3 * ARR + prow);
    __syncthreads();

#pragma unroll 2
    for (int it = 0; it < 16; ++it) {
        const uint32_t stg = (it & 1) ? (uint32_t)SSTG : 0u;

        if (it < 15) {
            const float* an  = ag + (it + 1) * 32;
            const float* wg2 = wg + (it + 1) * 32;
            pa[0] = ((const float4*)an)[0];
            pa[1] = ((const float4*)an)[1];
            pw[0] = ((const float4*)wg2)[0];
            pw[1] = ((const float4*)wg2)[1];
        }

        // ---- MMA phase on stage stg ----
        uint32_t bfr[2][2][4];
#pragma unroll
        for (int lvl = 0; lvl < 2; ++lvl)
#pragma unroll
            for (int ks = 0; ks < 2; ++ks) {
                const uint32_t addr = sb + 4 * (stg + (2 + lvl) * ARR +
                                                b_off + ks * 8);
                LDSM_X4(bfr[lvl][ks], addr);
            }

#pragma unroll
        for (int mt = 0; mt < 4; ++mt) {
            uint32_t af[2][2][4];   // [lvl][ks][4]
#pragma unroll
            for (int lvl = 0; lvl < 2; ++lvl)
#pragma unroll
                for (int ks = 0; ks < 2; ++ks) {
                    const uint32_t addr = sb + 4 * (stg + lvl * ARR + a_off +
                                                    ks * 8 + mt * 320);
                    LDSM_X4(af[lvl][ks], addr);
                }
#pragma unroll
            for (int nt = 0; nt < 2; ++nt) {
                const int so = nt << 1;
                float d[4];
                // 6-MMA fresh chain, small terms first
                MMA_ZERO(d, af[1][0], bfr[0][0][so], bfr[0][0][so + 1]);  // a1b0 k0
                MMA_ACC(d, af[1][1], bfr[0][1][so], bfr[0][1][so + 1]);   // a1b0 k1
                MMA_ACC(d, af[0][0], bfr[1][0][so], bfr[1][0][so + 1]);   // a0b1 k0
                MMA_ACC(d, af[0][1], bfr[1][1][so], bfr[1][1][so + 1]);   // a0b1 k1
                MMA_ACC(d, af[0][0], bfr[0][0][so], bfr[0][0][so + 1]);   // a0b0 k0
                MMA_ACC(d, af[0][1], bfr[0][1][so], bfr[0][1][so + 1]);   // a0b0 k1
                acc[mt][nt][0] += d[0];
                acc[mt][nt][1] += d[1];
                acc[mt][nt][2] += d[2];
                acc[mt][nt][3] += d[3];
            }
        }

        // ---- producer phase: fill other stage ----
        if (it < 15) {
            const uint32_t nst = (it & 1) ? 0u : (uint32_t)SSTG;
            split_store_q(pa, smem + nst + prow, smem + nst + ARR + prow);
            split_store_q(pw, smem + nst + 2 * ARR + prow,
                              smem + nst + 3 * ARR + prow);
        }
        __syncthreads();
    }

    // epilogue: add bias, write Y
    const int q = lane & 3;
    const int r = lane >> 2;
#pragma unroll
    for (int nt = 0; nt < 2; ++nt) {
        const int col = n0 + (wn << 4) + (nt << 3) + (q << 1);
        const float2 bb = *(const float2*)&bias[col];
#pragma unroll
        for (int mt = 0; mt < 4; ++mt) {
            const int rrow = m0 + (wm << 6) + (mt << 4) + r;
            float2 v0, v1;
            v0.x = acc[mt][nt][0] + bb.x;
            v0.y = acc[mt][nt][1] + bb.y;
            v1.x = acc[mt][nt][2] + bb.x;
            v1.y = acc[mt][nt][3] + bb.y;
            *(float2*)&g_y[(size_t)rrow * 512 + col]       = v0;
            *(float2*)&g_y[(size_t)(rrow + 8) * 512 + col] = v1;
        }
    }
}

// ---------------------------------------------------------------------------
// Bidirectional LIF scan + marginal-column flagging (per-(h,b) e-lists)
// ---------------------------------------------------------------------------
__global__ __launch_bounds__(256) void lif_scan_kernel(float* __restrict__ out)
{
    const int g = blockIdx.x * 256 + threadIdx.x;
    const int e = g & (DD - 1);
    const int b = (g >> 9) & (BB - 1);
    const int h = g >> 12;

    const size_t base = ((size_t)h * WD * BB + b) * DD + e;
    const float* yp = g_y + base;
    const size_t wstride = (size_t)BB * DD;

    unsigned fw[4] = {0u, 0u, 0u, 0u};
    unsigned bw[4] = {0u, 0u, 0u, 0u};
    bool flag = false;

    {
        float v = 0.0f;
#pragma unroll 8
        for (int w = 0; w < WD; ++w) {
            float yt = yp[(size_t)w * wstride];
            v = v + (yt - v) * 0.5f;
            flag |= (fabsf(v - 1.0f) < GUARD);
            if (v - 1.0f >= 0.0f) {
                fw[w >> 5] |= 1u << (w & 31);
                v = 0.0f;
            }
        }
    }
    {
        float v = 0.0f;
#pragma unroll 8
        for (int w = WD - 1; w >= 0; --w) {
            float yt = yp[(size_t)w * wstride];
            v = v + (yt - v) * 0.5f;
            flag |= (fabsf(v - 1.0f) < GUARD);
            if (v - 1.0f >= 0.0f) {
                bw[w >> 5] |= 1u << (w & 31);
                v = 0.0f;
            }
        }
    }

    float* op = out + base;
#pragma unroll
    for (int w = 0; w < WD; ++w) {
        float s = (float)(((fw[w >> 5] >> (w & 31)) & 1u) +
                          ((bw[w >> 5] >> (w & 31)) & 1u));
        op[(size_t)w * wstride] = s;
    }

    if (flag) {
        const int hb = g >> 9;
        int idx = atomicAdd(&g_ecnt[hb], 1);
        if (idx < CAP) g_elist[hb][idx] = (unsigned short)e;
    }
}

// ---------------------------------------------------------------------------
// Correction: one block per (h,b); recompute flagged e-columns exactly
// (ascending-k fp32 scalar FMA), redo both scans, overwrite out.
// ---------------------------------------------------------------------------
#define CSM_XS 0
#define CSM_WS (64 * 128)
#define CSM_YB (CSM_WS + 8 * 512)
#define CSM_TOTAL ((CSM_YB + 8 * 128) * 4)   // 53248 B

__global__ __launch_bounds__(256) void correct_kernel(
    const float* __restrict__ x,
    const float* __restrict__ Wl,
    const float* __restrict__ bias,
    float* __restrict__ out)
{
    extern __shared__ float csm[];
    float* xs   = csm + CSM_XS;   // [kk 0..63][w 0..127]
    float* ws   = csm + CSM_WS;   // [warp][512]
    float* ybuf = csm + CSM_YB;   // [warp][128]

    const int hb = blockIdx.x;
    int cnt = g_ecnt[hb];
    if (cnt <= 0) return;
    if (cnt > CAP) cnt = CAP;

    const int h = hb >> 3, b = hb & 7;
    const int tid = threadIdx.x, wrp = tid >> 5, lane = tid & 31;
    const size_t cbase = ((size_t)(h * WD) * BB + b) * DD;

    for (int ebase = 0; ebase < cnt; ebase += 8) {
        int e = -1;
        float be = 0.0f;
        if (ebase + wrp < cnt) {
            e = g_elist[hb][ebase + wrp];
            be = bias[e];
            const float4* wr = (const float4*)(Wl + (size_t)e * 512);
            float4* wd = (float4*)(ws + wrp * 512);
            for (int j = lane; j < 128; j += 32) wd[j] = wr[j];
        }

        float a0 = 0.f, a1 = 0.f, a2 = 0.f, a3 = 0.f;
        for (int ck = 0; ck < 8; ++ck) {
            __syncthreads();
#pragma unroll
            for (int i = 0; i < 2; ++i) {
                const int w = (tid >> 2) + i * 64;
                const float4* xr = (const float4*)(x + cbase +
                                                   (size_t)w * 4096 + ck * 64);
#pragma unroll
                for (int j = 0; j < 4; ++j) {
                    const int k4 = (tid & 3) + j * 4;
                    float4 v = xr[k4];
                    xs[(k4 * 4 + 0) * 128 + w] = v.x;
                    xs[(k4 * 4 + 1) * 128 + w] = v.y;
                    xs[(k4 * 4 + 2) * 128 + w] = v.z;
                    xs[(k4 * 4 + 3) * 128 + w] = v.w;
                }
            }
            __syncthreads();
            if (e >= 0) {
                const float* wc = ws + wrp * 512 + ck * 64;
                for (int kk = 0; kk < 64; ++kk) {
                    const float wv = wc[kk];
                    a0 = fmaf(xs[kk * 128 + lane],      wv, a0);
                    a1 = fmaf(xs[kk * 128 + lane + 32], wv, a1);
                    a2 = fmaf(xs[kk * 128 + lane + 64], wv, a2);
                    a3 = fmaf(xs[kk * 128 + lane + 96], wv, a3);
                }
            }
        }

        unsigned bits[4] = {0u, 0u, 0u, 0u};
        if (e >= 0) {
            ybuf[wrp * 128 + lane]      = a0 + be;
            ybuf[wrp * 128 + lane + 32] = a1 + be;
            ybuf[wrp * 128 + lane + 64] = a2 + be;
            ybuf[wrp * 128 + lane + 96] = a3 + be;
        }
        __syncwarp();
        if (e >= 0 && lane < 2) {
            float v = 0.0f;
            for (int i = 0; i < WD; ++i) {
                const int w = lane ? (WD - 1 - i) : i;
                float yt = ybuf[wrp * 128 + w];
                v = v + (yt - v) * 0.5f;
                if (v - 1.0f >= 0.0f) { bits[w >> 5] |= 1u << (w & 31); v = 0.0f; }
            }
        }
        unsigned fwv[4], bwv[4];
#pragma unroll
        for (int i = 0; i < 4; ++i) {
            fwv[i] = __shfl_sync(0xFFFFFFFFu, bits[i], 0);
            bwv[i] = __shfl_sync(0xFFFFFFFFu, bits[i], 1);
        }
        if (e >= 0) {
#pragma unroll
            for (int c = 0; c < 4; ++c) {
                const int w = lane + 32 * c;
                float s = (float)(((fwv[w >> 5] >> (w & 31)) & 1u) +
                                  ((bwv[w >> 5] >> (w & 31)) & 1u));
                out[cbase + (size_t)w * 4096 + e] = s;
            }
        }
        __syncthreads();
    }
}

extern "C" void kernel_launch(void* const* d_in, const int* in_sizes, int n_in,
                              void* d_out, int out_size)
{
    const float* x    = (const float*)d_in[0];   // (16384, 8, 512) fp32
    const float* Wlin = (const float*)d_in[1];   // (512, 512) fp32
    const float* blin = (const float*)d_in[2];   // (512,) fp32
    float* out = (float*)d_out;

    cudaFuncSetAttribute(gemm_tc_kernel,
                         cudaFuncAttributeMaxDynamicSharedMemorySize, SMEM_GEMM);
    cudaFuncSetAttribute(correct_kernel,
                         cudaFuncAttributeMaxDynamicSharedMemorySize, CSM_TOTAL);

    dim3 ggrid(4, 1024);   // N/128, M/128
    gemm_tc_kernel<<<ggrid, 512, SMEM_GEMM>>>(x, Wlin, blin);

    lif_scan_kernel<<<(HH * BB * DD) / 256, 256>>>(out);

    correct_kernel<<<HH * BB, 256, CSM_TOTAL>>>(x, Wlin, blin, out);
}

// round 11
// speedup vs baseline: 1.5434x; 1.1660x over previous
#include <cuda_runtime.h>
#include <cuda_fp16.h>
#include <cstdint>

// Problem dims
#define HH 128
#define WD 128
#define BB 8
#define DD 512
#define M_TOTAL (HH * WD * BB)   // 131072 rows
#define X_ELEMS ((size_t)M_TOTAL * DD)
#define W_ELEMS ((size_t)DD * DD)
#define GUARD 2e-5f
#define CAP 128

// Scratch
__device__ float g_y[(size_t)M_TOTAL * DD];
__device__ __half g_x0[X_ELEMS];
__device__ __half g_x1[X_ELEMS];
__device__ __half g_w0[W_ELEMS];
__device__ __half g_w1[W_ELEMS];
__device__ int g_ecnt[HH * BB];
__device__ unsigned short g_elist[HH * BB][CAP];

// ---------------------------------------------------------------------------
// MMA / LDSM / cp.async macros
// ---------------------------------------------------------------------------
#define MMA_ZERO(d, a, b0, b1)                                               \
    asm volatile(                                                            \
        "mma.sync.aligned.m16n8k16.row.col.f32.f16.f16.f32 "                \
        "{%0,%1,%2,%3}, {%4,%5,%6,%7}, {%8,%9}, {%10,%10,%10,%10};"         \
        : "=f"((d)[0]), "=f"((d)[1]), "=f"((d)[2]), "=f"((d)[3])             \
        : "r"((a)[0]), "r"((a)[1]), "r"((a)[2]), "r"((a)[3]),                \
          "r"(b0), "r"(b1), "f"(0.0f))

#define MMA_ACC(d, a, b0, b1)                                                \
    asm volatile(                                                            \
        "mma.sync.aligned.m16n8k16.row.col.f32.f16.f16.f32 "                \
        "{%0,%1,%2,%3}, {%4,%5,%6,%7}, {%8,%9}, {%0,%1,%2,%3};"             \
        : "+f"((d)[0]), "+f"((d)[1]), "+f"((d)[2]), "+f"((d)[3])             \
        : "r"((a)[0]), "r"((a)[1]), "r"((a)[2]), "r"((a)[3]),                \
          "r"(b0), "r"(b1))

#define LDSM_X4(r, addr)                                                     \
    asm volatile(                                                            \
        "ldmatrix.sync.aligned.m8n8.x4.shared.b16 {%0,%1,%2,%3}, [%4];"     \
        : "=r"((r)[0]), "=r"((r)[1]), "=r"((r)[2]), "=r"((r)[3])             \
        : "r"(addr))

#define CP_ASYNC(dst, src)                                                   \
    asm volatile("cp.async.cg.shared.global [%0], [%1], 16;"                \
                 :: "r"(dst), "l"(src) : "memory")
#define CP_COMMIT()  asm volatile("cp.async.commit_group;" ::: "memory")
#define CP_WAIT0()   asm volatile("cp.async.wait_group 0;" ::: "memory")

// SMEM geometry (uint32 units): [row 0..127][kp 0..15] stride 20.
// 4 arrays per stage (A0, A1, W0, W1), 2 stages.
#define RST  20
#define ARR  (128 * RST)        // 2560 u32 = 10240 B
#define SSTG (4 * ARR)
#define SMEM_GEMM (2 * SSTG * 4)  // 81920 B

__device__ __forceinline__ uint32_t smem_u32(const void* p) {
    uint32_t a;
    asm("{ .reg .u64 t; cvta.to.shared.u64 t, %1; cvt.u32.u64 %0, t; }"
        : "=r"(a) : "l"(p));
    return a;
}

// ---------------------------------------------------------------------------
// Pre-split: fp32 -> fp16 hi/lo (exactly R10's split3 numerics)
// ---------------------------------------------------------------------------
__global__ __launch_bounds__(256) void split_kernel(
    const float* __restrict__ x, const float* __restrict__ w)
{
    const int tid = threadIdx.x;
    if (blockIdx.x == 0) {
        for (int i = tid; i < HH * BB; i += 256) g_ecnt[i] = 0;
    }
    size_t i4 = ((size_t)blockIdx.x * 256 + tid) * 4;
    const float* src;
    __half *d0, *d1;
    if (i4 < X_ELEMS) {
        src = x + i4; d0 = g_x0 + i4; d1 = g_x1 + i4;
    } else {
        i4 -= X_ELEMS;
        if (i4 >= W_ELEMS) return;
        src = w + i4; d0 = g_w0 + i4; d1 = g_w1 + i4;
    }
    float4 v = *(const float4*)src;
    const float f[4] = {v.x, v.y, v.z, v.w};
    unsigned short h[4], l[4];
#pragma unroll
    for (int j = 0; j < 4; ++j) {
        __half hh = __float2half_rn(f[j]);
        __half ll = __float2half_rn(f[j] - __half2float(hh));
        h[j] = __half_as_ushort(hh);
        l[j] = __half_as_ushort(ll);
    }
    *(uint2*)d0 = make_uint2((uint32_t)h[0] | ((uint32_t)h[1] << 16),
                             (uint32_t)h[2] | ((uint32_t)h[3] << 16));
    *(uint2*)d1 = make_uint2((uint32_t)l[0] | ((uint32_t)l[1] << 16),
                             (uint32_t)l[2] | ((uint32_t)l[3] << 16));
}

// ---------------------------------------------------------------------------
// GEMM: Y[m,n] = sum_k X[m,k]*Wlin[n,k] + bias[n]
// fp16 2-level split, 3 passes; 6-MMA fresh chain per (mt,nt) per 32-k, FADD
// master. CTA 128x128, BK=32, 8 warps (2M x 4N), warp tile 64x32, ldmatrix,
// cp.async producer, double-buffered, target 2 CTAs/SM.
// ---------------------------------------------------------------------------
__global__ __launch_bounds__(256, 2) void gemm_tc_kernel(
    const float* __restrict__ bias)
{
    extern __shared__ uint32_t smem[];
    const uint32_t sb = smem_u32(smem);

    const int tid  = threadIdx.x;
    const int lane = tid & 31;
    const int wid  = tid >> 5;
    const int wm   = wid >> 2;        // 0..1
    const int wn   = wid & 3;         // 0..3

    const int m0 = blockIdx.y << 7;
    const int n0 = blockIdx.x << 7;

    // producer: row = tid>>1, chunk pair = (tid&1)*2 (two 16B chunks per array)
    const int prow  = tid >> 1;
    const int cpair = (tid & 1) << 1;
    const __half* src[4];
    src[0] = g_x0 + (size_t)(m0 + prow) * 512 + cpair * 8;
    src[1] = g_x1 + (size_t)(m0 + prow) * 512 + cpair * 8;
    src[2] = g_w0 + (size_t)(n0 + prow) * 512 + cpair * 8;
    src[3] = g_w1 + (size_t)(n0 + prow) * 512 + cpair * 8;
    const uint32_t dstb = sb + 4 * (prow * RST + cpair * 4);

    // consumer address bases (uint32 offsets)
    const uint32_t a_off = ((wm << 6) + (lane & 15)) * RST + ((lane >> 4) << 2);
    const uint32_t b_off = ((wn << 5) + ((lane >> 4) << 3) + (lane & 7)) * RST +
                           (((lane >> 3) & 1) << 2);

    float acc[4][4][4];
#pragma unroll
    for (int mt = 0; mt < 4; ++mt)
#pragma unroll
        for (int nt = 0; nt < 4; ++nt)
#pragma unroll
            for (int r = 0; r < 4; ++r) acc[mt][nt][r] = 0.0f;

    // prologue: issue stage 0 (k-window 0)
#pragma unroll
    for (int arr = 0; arr < 4; ++arr) {
#pragma unroll
        for (int c = 0; c < 2; ++c)
            CP_ASYNC(dstb + 4 * (arr * ARR) + c * 16, src[arr] + c * 8);
    }
    CP_COMMIT();

    for (int it = 0; it < 16; ++it) {
        const uint32_t stg = (it & 1) ? (uint32_t)SSTG : 0u;

        CP_WAIT0();
        __syncthreads();   // stage it ready everywhere; stage it+1 buf free

        if (it < 15) {
            const uint32_t nst = (it & 1) ? 0u : (uint32_t)SSTG;
            const int koff = (it + 1) * 32;   // halfs
#pragma unroll
            for (int arr = 0; arr < 4; ++arr) {
#pragma unroll
                for (int c = 0; c < 2; ++c)
                    CP_ASYNC(dstb + 4 * (nst + arr * ARR) + c * 16,
                             src[arr] + koff + c * 8);
            }
            CP_COMMIT();
        }

        // ---- MMA phase on stage stg ----
        uint32_t bfr[2][2][2][4];   // [lvl][ks][ntp][4]
#pragma unroll
        for (int lvl = 0; lvl < 2; ++lvl)
#pragma unroll
            for (int ks = 0; ks < 2; ++ks)
#pragma unroll
                for (int ntp = 0; ntp < 2; ++ntp) {
                    const uint32_t addr = sb + 4 * (stg + (2 + lvl) * ARR +
                                                    b_off + ks * 8 + ntp * 320);
                    LDSM_X4(bfr[lvl][ks][ntp], addr);
                }

#pragma unroll
        for (int mt = 0; mt < 4; ++mt) {
            uint32_t af[2][2][4];   // [lvl][ks][4]
#pragma unroll
            for (int lvl = 0; lvl < 2; ++lvl)
#pragma unroll
                for (int ks = 0; ks < 2; ++ks) {
                    const uint32_t addr = sb + 4 * (stg + lvl * ARR + a_off +
                                                    ks * 8 + mt * 320);
                    LDSM_X4(af[lvl][ks], addr);
                }
#pragma unroll
            for (int nt = 0; nt < 4; ++nt) {
                const int ntp = nt >> 1, so = (nt & 1) << 1;
                float d[4];
                // 6-MMA fresh chain, small terms first (R10 ordering)
                MMA_ZERO(d, af[1][0], bfr[0][0][ntp][so], bfr[0][0][ntp][so + 1]);
                MMA_ACC(d, af[1][1], bfr[0][1][ntp][so], bfr[0][1][ntp][so + 1]);
                MMA_ACC(d, af[0][0], bfr[1][0][ntp][so], bfr[1][0][ntp][so + 1]);
                MMA_ACC(d, af[0][1], bfr[1][1][ntp][so], bfr[1][1][ntp][so + 1]);
                MMA_ACC(d, af[0][0], bfr[0][0][ntp][so], bfr[0][0][ntp][so + 1]);
                MMA_ACC(d, af[0][1], bfr[0][1][ntp][so], bfr[0][1][ntp][so + 1]);
                acc[mt][nt][0] += d[0];
                acc[mt][nt][1] += d[1];
                acc[mt][nt][2] += d[2];
                acc[mt][nt][3] += d[3];
            }
        }
    }

    // epilogue: add bias, write Y
    const int q = lane & 3;
    const int r = lane >> 2;
#pragma unroll
    for (int nt = 0; nt < 4; ++nt) {
        const int col = n0 + (wn << 5) + (nt << 3) + (q << 1);
        const float2 bb = *(const float2*)&bias[col];
#pragma unroll
        for (int mt = 0; mt < 4; ++mt) {
            const int rrow = m0 + (wm << 6) + (mt << 4) + r;
            float2 v0, v1;
            v0.x = acc[mt][nt][0] + bb.x;
            v0.y = acc[mt][nt][1] + bb.y;
            v1.x = acc[mt][nt][2] + bb.x;
            v1.y = acc[mt][nt][3] + bb.y;
            *(float2*)&g_y[(size_t)rrow * 512 + col]       = v0;
            *(float2*)&g_y[(size_t)(rrow + 8) * 512 + col] = v1;
        }
    }
}

// ---------------------------------------------------------------------------
// Bidirectional LIF scan + marginal-column flagging (per-(h,b) e-lists)
// ---------------------------------------------------------------------------
__global__ __launch_bounds__(256) void lif_scan_kernel(float* __restrict__ out)
{
    const int g = blockIdx.x * 256 + threadIdx.x;
    const int e = g & (DD - 1);
    const int b = (g >> 9) & (BB - 1);
    const int h = g >> 12;

    const size_t base = ((size_t)h * WD * BB + b) * DD + e;
    const float* yp = g_y + base;
    const size_t wstride = (size_t)BB * DD;

    unsigned fw[4] = {0u, 0u, 0u, 0u};
    unsigned bw[4] = {0u, 0u, 0u, 0u};
    bool flag = false;

    {
        float v = 0.0f;
#pragma unroll 8
        for (int w = 0; w < WD; ++w) {
            float yt = yp[(size_t)w * wstride];
            v = v + (yt - v) * 0.5f;
            flag |= (fabsf(v - 1.0f) < GUARD);
            if (v - 1.0f >= 0.0f) {
                fw[w >> 5] |= 1u << (w & 31);
                v = 0.0f;
            }
        }
    }
    {
        float v = 0.0f;
#pragma unroll 8
        for (int w = WD - 1; w >= 0; --w) {
            float yt = yp[(size_t)w * wstride];
            v = v + (yt - v) * 0.5f;
            flag |= (fabsf(v - 1.0f) < GUARD);
            if (v - 1.0f >= 0.0f) {
                bw[w >> 5] |= 1u << (w & 31);
                v = 0.0f;
            }
        }
    }

    float* op = out + base;
#pragma unroll
    for (int w = 0; w < WD; ++w) {
        float s = (float)(((fw[w >> 5] >> (w & 31)) & 1u) +
                          ((bw[w >> 5] >> (w & 31)) & 1u));
        op[(size_t)w * wstride] = s;
    }

    if (flag) {
        const int hb = g >> 9;
        int idx = atomicAdd(&g_ecnt[hb], 1);
        if (idx < CAP) g_elist[hb][idx] = (unsigned short)e;
    }
}

// ---------------------------------------------------------------------------
// Correction: one block per (h,b); recompute flagged e-columns exactly
// (ascending-k fp32 scalar FMA), redo both scans, overwrite out.
// ---------------------------------------------------------------------------
#define CSM_XS 0
#define CSM_WS (64 * 128)
#define CSM_YB (CSM_WS + 8 * 512)
#define CSM_TOTAL ((CSM_YB + 8 * 128) * 4)   // 53248 B

__global__ __launch_bounds__(256) void correct_kernel(
    const float* __restrict__ x,
    const float* __restrict__ Wl,
    const float* __restrict__ bias,
    float* __restrict__ out)
{
    extern __shared__ float csm[];
    float* xs   = csm + CSM_XS;
    float* ws   = csm + CSM_WS;
    float* ybuf = csm + CSM_YB;

    const int hb = blockIdx.x;
    int cnt = g_ecnt[hb];
    if (cnt <= 0) return;
    if (cnt > CAP) cnt = CAP;

    const int h = hb >> 3, b = hb & 7;
    const int tid = threadIdx.x, wrp = tid >> 5, lane = tid & 31;
    const size_t cbase = ((size_t)(h * WD) * BB + b) * DD;

    for (int ebase = 0; ebase < cnt; ebase += 8) {
        int e = -1;
        float be = 0.0f;
        if (ebase + wrp < cnt) {
            e = g_elist[hb][ebase + wrp];
            be = bias[e];
            const float4* wr = (const float4*)(Wl + (size_t)e * 512);
            float4* wd = (float4*)(ws + wrp * 512);
            for (int j = lane; j < 128; j += 32) wd[j] = wr[j];
        }

        float a0 = 0.f, a1 = 0.f, a2 = 0.f, a3 = 0.f;
        for (int ck = 0; ck < 8; ++ck) {
            __syncthreads();
#pragma unroll
            for (int i = 0; i < 2; ++i) {
                const int w = (tid >> 2) + i * 64;
                const float4* xr = (const float4*)(x + cbase +
                                                   (size_t)w * 4096 + ck * 64);
#pragma unroll
                for (int j = 0; j < 4; ++j) {
                    const int k4 = (tid & 3) + j * 4;
                    float4 v = xr[k4];
                    xs[(k4 * 4 + 0) * 128 + w] = v.x;
                    xs[(k4 * 4 + 1) * 128 + w] = v.y;
                    xs[(k4 * 4 + 2) * 128 + w] = v.z;
                    xs[(k4 * 4 + 3) * 128 + w] = v.w;
                }
            }
            __syncthreads();
            if (e >= 0) {
                const float* wc = ws + wrp * 512 + ck * 64;
                for (int kk = 0; kk < 64; ++kk) {
                    const float wv = wc[kk];
                    a0 = fmaf(xs[kk * 128 + lane],      wv, a0);
                    a1 = fmaf(xs[kk * 128 + lane + 32], wv, a1);
                    a2 = fmaf(xs[kk * 128 + lane + 64], wv, a2);
                    a3 = fmaf(xs[kk * 128 + lane + 96], wv, a3);
                }
            }
        }

        unsigned bits[4] = {0u, 0u, 0u, 0u};
        if (e >= 0) {
            ybuf[wrp * 128 + lane]      = a0 + be;
            ybuf[wrp * 128 + lane + 32] = a1 + be;
            ybuf[wrp * 128 + lane + 64] = a2 + be;
            ybuf[wrp * 128 + lane + 96] = a3 + be;
        }
        __syncwarp();
        if (e >= 0 && lane < 2) {
            float v = 0.0f;
            for (int i = 0; i < WD; ++i) {
                const int w = lane ? (WD - 1 - i) : i;
                float yt = ybuf[wrp * 128 + w];
                v = v + (yt - v) * 0.5f;
                if (v - 1.0f >= 0.0f) { bits[w >> 5] |= 1u << (w & 31); v = 0.0f; }
            }
        }
        unsigned fwv[4], bwv[4];
#pragma unroll
        for (int i = 0; i < 4; ++i) {
            fwv[i] = __shfl_sync(0xFFFFFFFFu, bits[i], 0);
            bwv[i] = __shfl_sync(0xFFFFFFFFu, bits[i], 1);
        }
        if (e >= 0) {
#pragma unroll
            for (int c = 0; c < 4; ++c) {
                const int w = lane + 32 * c;
                float s = (float)(((fwv[w >> 5] >> (w & 31)) & 1u) +
                                  ((bwv[w >> 5] >> (w & 31)) & 1u));
                out[cbase + (size_t)w * 4096 + e] = s;
            }
        }
        __syncthreads();
    }
}

extern "C" void kernel_launch(void* const* d_in, const int* in_sizes, int n_in,
                              void* d_out, int out_size)
{
    const float* x    = (const float*)d_in[0];   // (16384, 8, 512) fp32
    const float* Wlin = (const float*)d_in[1];   // (512, 512) fp32
    const float* blin = (const float*)d_in[2];   // (512,) fp32
    float* out = (float*)d_out;

    cudaFuncSetAttribute(gemm_tc_kernel,
                         cudaFuncAttributeMaxDynamicSharedMemorySize, SMEM_GEMM);
    cudaFuncSetAttribute(correct_kernel,
                         cudaFuncAttributeMaxDynamicSharedMemorySize, CSM_TOTAL);

    // pre-split X and W into fp16 hi/lo
    const int xblocks = (int)(X_ELEMS / 1024);          // 65536
    const int wblocks = (int)(W_ELEMS / 1024);          // 256
    split_kernel<<<xblocks + wblocks, 256>>>(x, Wlin);

    dim3 ggrid(4, 1024);   // N/128, M/128
    gemm_tc_kernel<<<ggrid, 256, SMEM_GEMM>>>(blin);

    lif_scan_kernel<<<(HH * BB * DD) / 256, 256>>>(out);

    correct_kernel<<<HH * BB, 256, CSM_TOTAL>>>(x, Wlin, blin, out);
}